// round 1
// baseline (speedup 1.0000x reference)
#include <cuda_runtime.h>
#include <cstdint>

#define SEQ    2048
#define BATCH  512
#define INPT   64
#define HIDDEN 128
#define KTOT   192   // INPT + HIDDEN combined reduction dim
#define KHALF  96    // per-thread K slice (2-way K split)
#define BB     4     // batch elements per block
#define NBLK   (BATCH / BB)   // 128 blocks
#define NTHR   256            // 128 j-lanes x 2 k-halves

// ---- packed f32x2 helpers (sm_103a) ----
__device__ __forceinline__ unsigned long long ffma2(unsigned long long a,
                                                    unsigned long long b,
                                                    unsigned long long c) {
    unsigned long long d;
    asm("fma.rn.f32x2 %0, %1, %2, %3;" : "=l"(d) : "l"(a), "l"(b), "l"(c));
    return d;
}
__device__ __forceinline__ unsigned long long pack2(float lo, float hi) {
    unsigned long long v;
    asm("mov.b64 %0, {%1, %2};" : "=l"(v) : "f"(lo), "f"(hi));
    return v;
}
__device__ __forceinline__ float2 unpack2(unsigned long long v) {
    float2 r;
    asm("mov.b64 {%0, %1}, %2;" : "=f"(r.x), "=f"(r.y) : "l"(v));
    return r;
}

// accurate-enough tanh: MUFU.EX2 + fast divide, rel err ~1e-6
__device__ __forceinline__ float tanh_fast(float z) {
    float az = fabsf(z);
    float e  = __expf(-2.0f * az);
    float r  = __fdividef(1.0f - e, 1.0f + e);
    return copysignf(r, z);
}

__global__ void __launch_bounds__(NTHR, 1)
rnn_kernel(const float* __restrict__ xs,
           const float* __restrict__ W_ih,
           const float* __restrict__ W_hh,
           const float* __restrict__ b_ih,
           const float* __restrict__ b_hh,
           const float* __restrict__ W_out,
           const float* __restrict__ b_out,
           float* __restrict__ out) {
    // v[buf][b][k]: k<64 = x(t), k>=64 = h(t). Double-buffered over time.
    __shared__ __align__(16) float v[2][BB][KTOT];
    __shared__ float part[2][BB][HIDDEN];
    __shared__ float bias[HIDDEN];

    const int tid   = threadIdx.x;
    const int j     = tid & (HIDDEN - 1);   // output neuron this thread owns
    const int kh    = tid >> 7;             // which K half (0 or 1)
    const int k0    = kh * KHALF;
    const int bbase = blockIdx.x * BB;

    // ---- one-time init ----
    if (tid < HIDDEN) {
        bias[tid] = b_ih[tid] + b_hh[tid];
        #pragma unroll
        for (int b = 0; b < BB; b++) v[0][b][INPT + tid] = 0.0f;  // h0 = 0
    }
    if (tid < BB * 16) {  // load x(0): 4 batches x 16 float4
        int b  = tid >> 4;
        int i4 = (tid & 15) * 4;
        float4 q = *reinterpret_cast<const float4*>(
            xs + ((size_t)0 * BATCH + bbase + b) * INPT + i4);
        *reinterpret_cast<float4*>(&v[0][b][i4]) = q;
    }

    // Preload this thread's 96 weights into registers, packed as f32x2 pairs.
    // Combined weight row: k<64 -> W_ih[j][k], k>=64 -> W_hh[j][k-64].
    unsigned long long w2[KHALF / 2];
    #pragma unroll
    for (int i = 0; i < KHALF / 2; i++) {
        int ka = k0 + 2 * i;
        int kb = ka + 1;
        float wa = (ka < INPT) ? W_ih[j * INPT + ka] : W_hh[j * HIDDEN + (ka - INPT)];
        float wb = (kb < INPT) ? W_ih[j * INPT + kb] : W_hh[j * HIDDEN + (kb - INPT)];
        w2[i] = pack2(wa, wb);
    }
    __syncthreads();

    // ---- main recurrence ----
    int cur = 0;
    for (int t = 0; t < SEQ; ++t) {
        const int nxt = cur ^ 1;

        // Prefetch x(t+1) into the other buffer (safe: everyone passed the
        // barrier ending step t-1, so v[nxt]'s x-region is no longer read).
        if (tid < BB * 16) {
            int b  = tid >> 4;
            int i4 = (tid & 15) * 4;
            if (t + 1 < SEQ) {
                const float* src = xs + ((size_t)(t + 1) * BATCH + bbase + b) * INPT + i4;
                unsigned dst = (unsigned)__cvta_generic_to_shared(&v[nxt][b][i4]);
                asm volatile("cp.async.ca.shared.global [%0], [%1], 16;"
                             :: "r"(dst), "l"(src));
            }
            asm volatile("cp.async.commit_group;" ::);
        }

        // Partial dot products: this thread's K slice against all BB batches.
        // Operands read from shared as packed f32x2 pairs (LDS.128, no repack).
        unsigned long long acc[BB][2];
        #pragma unroll
        for (int b = 0; b < BB; b++) { acc[b][0] = 0ull; acc[b][1] = 0ull; }

        const ulonglong2* vb0 = reinterpret_cast<const ulonglong2*>(&v[cur][0][k0]);
        const ulonglong2* vb1 = reinterpret_cast<const ulonglong2*>(&v[cur][1][k0]);
        const ulonglong2* vb2 = reinterpret_cast<const ulonglong2*>(&v[cur][2][k0]);
        const ulonglong2* vb3 = reinterpret_cast<const ulonglong2*>(&v[cur][3][k0]);

        #pragma unroll
        for (int i = 0; i < KHALF / 4; i++) {   // 24 iters, 4 k's each
            ulonglong2 q0 = vb0[i];
            ulonglong2 q1 = vb1[i];
            ulonglong2 q2 = vb2[i];
            ulonglong2 q3 = vb3[i];
            acc[0][0] = ffma2(w2[2 * i],     q0.x, acc[0][0]);
            acc[0][1] = ffma2(w2[2 * i + 1], q0.y, acc[0][1]);
            acc[1][0] = ffma2(w2[2 * i],     q1.x, acc[1][0]);
            acc[1][1] = ffma2(w2[2 * i + 1], q1.y, acc[1][1]);
            acc[2][0] = ffma2(w2[2 * i],     q2.x, acc[2][0]);
            acc[2][1] = ffma2(w2[2 * i + 1], q2.y, acc[2][1]);
            acc[3][0] = ffma2(w2[2 * i],     q3.x, acc[3][0]);
            acc[3][1] = ffma2(w2[2 * i + 1], q3.y, acc[3][1]);
        }

        #pragma unroll
        for (int b = 0; b < BB; b++) {
            float2 p0 = unpack2(acc[b][0]);
            float2 p1 = unpack2(acc[b][1]);
            part[kh][b][j] = (p0.x + p0.y) + (p1.x + p1.y);
        }
        __syncthreads();

        // Combine halves, activate, write h(t+1).
        if (tid < HIDDEN) {
            #pragma unroll
            for (int b = 0; b < BB; b++) {
                float z = part[0][b][tid] + part[1][b][tid] + bias[tid];
                v[nxt][b][INPT + tid] = tanh_fast(z);
            }
        }
        asm volatile("cp.async.wait_group 0;" ::);
        __syncthreads();
        cur = nxt;
    }

    // ---- output projection: out[b] = h_final[b] . W_out + b_out ----
    // cur == 0 after an even number of steps; final h lives in v[cur].
    if (tid < 4 * 32) {
        int b = tid >> 5;
        int l = tid & 31;
        float s = 0.0f;
        #pragma unroll
        for (int m = 0; m < 4; m++) {
            int jj = l + 32 * m;
            s += v[cur][b][INPT + jj] * W_out[jj];
        }
        #pragma unroll
        for (int off = 16; off; off >>= 1)
            s += __shfl_down_sync(0xffffffffu, s, off);
        if (l == 0) out[bbase + b] = s + b_out[0];
    }
}

extern "C" void kernel_launch(void* const* d_in, const int* in_sizes, int n_in,
                              void* d_out, int out_size) {
    const float* xs    = (const float*)d_in[0];
    const float* W_ih  = (const float*)d_in[1];
    const float* W_hh  = (const float*)d_in[2];
    const float* b_ih  = (const float*)d_in[3];
    const float* b_hh  = (const float*)d_in[4];
    const float* W_out = (const float*)d_in[5];
    const float* b_out = (const float*)d_in[6];
    rnn_kernel<<<NBLK, NTHR>>>(xs, W_ih, W_hh, b_ih, b_hh, W_out, b_out,
                               (float*)d_out);
}

// round 2
// speedup vs baseline: 1.1267x; 1.1267x over previous
#include <cuda_runtime.h>
#include <cstdint>

#define SEQ    2048
#define BATCH  512
#define INPT   64
#define HIDDEN 128
#define KTOT   192            // INPT + HIDDEN combined reduction dim
#define NSPL   4              // K split ways
#define KQ     (KTOT / NSPL)  // 48 k per thread
#define BB     4              // batch elements per block
#define NBLK   (BATCH / BB)   // 128 blocks
#define NTHR   512            // 128 j-lanes x 4 k-quarters

// ---- packed f32x2 helpers (sm_103a) ----
__device__ __forceinline__ unsigned long long ffma2(unsigned long long a,
                                                    unsigned long long b,
                                                    unsigned long long c) {
    unsigned long long d;
    asm("fma.rn.f32x2 %0, %1, %2, %3;" : "=l"(d) : "l"(a), "l"(b), "l"(c));
    return d;
}
__device__ __forceinline__ unsigned long long pack2(float lo, float hi) {
    unsigned long long v;
    asm("mov.b64 %0, {%1, %2};" : "=l"(v) : "f"(lo), "f"(hi));
    return v;
}
__device__ __forceinline__ float2 unpack2(unsigned long long v) {
    float2 r;
    asm("mov.b64 {%0, %1}, %2;" : "=f"(r.x), "=f"(r.y) : "l"(v));
    return r;
}

// accurate-enough tanh: MUFU.EX2 + fast divide, rel err ~1e-6
__device__ __forceinline__ float tanh_fast(float z) {
    float az = fabsf(z);
    float e  = __expf(-2.0f * az);
    float r  = __fdividef(1.0f - e, 1.0f + e);
    return copysignf(r, z);
}

__global__ void __launch_bounds__(NTHR, 1)
rnn_kernel(const float* __restrict__ xs,
           const float* __restrict__ W_ih,
           const float* __restrict__ W_hh,
           const float* __restrict__ b_ih,
           const float* __restrict__ b_hh,
           const float* __restrict__ W_out,
           const float* __restrict__ b_out,
           float* __restrict__ out) {
    // v[buf][b][k]: k<64 = x(t), k>=64 = h(t). Double-buffered over time.
    __shared__ __align__(16) float v[2][BB][KTOT];
    __shared__ float part[NSPL][BB][HIDDEN];
    __shared__ float bias[HIDDEN];

    const int tid   = threadIdx.x;
    const int j     = tid & (HIDDEN - 1);   // output neuron this thread owns
    const int kh    = tid >> 7;             // which K quarter (0..3)
    const int k0    = kh * KQ;
    const int bbase = blockIdx.x * BB;

    // ---- one-time init ----
    if (tid < HIDDEN) {
        bias[tid] = b_ih[tid] + b_hh[tid];
        #pragma unroll
        for (int b = 0; b < BB; b++) v[0][b][INPT + tid] = 0.0f;  // h0 = 0
    }
    if (tid < BB * 16) {  // load x(0): 4 batches x 16 float4
        int b  = tid >> 4;
        int i4 = (tid & 15) * 4;
        float4 q = *reinterpret_cast<const float4*>(
            xs + ((size_t)bbase + b) * INPT + i4);
        *reinterpret_cast<float4*>(&v[0][b][i4]) = q;
    }

    // Preload this thread's 48 weights into registers, packed as f32x2 pairs.
    // Combined weight row: k<64 -> W_ih[j][k], k>=64 -> W_hh[j][k-64].
    unsigned long long w2[KQ / 2];
    #pragma unroll
    for (int i = 0; i < KQ / 2; i++) {
        int ka = k0 + 2 * i;
        int kb = ka + 1;
        float wa = (ka < INPT) ? W_ih[j * INPT + ka] : W_hh[j * HIDDEN + (ka - INPT)];
        float wb = (kb < INPT) ? W_ih[j * INPT + kb] : W_hh[j * HIDDEN + (kb - INPT)];
        w2[i] = pack2(wa, wb);
    }
    __syncthreads();

    // ---- main recurrence ----
    int cur = 0;
    for (int t = 0; t < SEQ; ++t) {
        const int nxt = cur ^ 1;

        // Prefetch x(t+1) into the other buffer (safe: everyone passed the
        // barrier ending step t-1, so v[nxt]'s x-region is no longer read).
        if (tid < BB * 16) {
            int b  = tid >> 4;
            int i4 = (tid & 15) * 4;
            if (t + 1 < SEQ) {
                const float* src = xs + ((size_t)(t + 1) * BATCH + bbase + b) * INPT + i4;
                unsigned dst = (unsigned)__cvta_generic_to_shared(&v[nxt][b][i4]);
                asm volatile("cp.async.ca.shared.global [%0], [%1], 16;"
                             :: "r"(dst), "l"(src));
            }
            asm volatile("cp.async.commit_group;" ::);
        }

        // Partial dot products: this thread's 48-k slice against all BB batches.
        // Operands read from shared as packed f32x2 pairs (LDS.128, broadcast
        // within a warp -> conflict-free).
        unsigned long long acc[BB][2];
        #pragma unroll
        for (int b = 0; b < BB; b++) { acc[b][0] = 0ull; acc[b][1] = 0ull; }

        const ulonglong2* vb0 = reinterpret_cast<const ulonglong2*>(&v[cur][0][k0]);
        const ulonglong2* vb1 = reinterpret_cast<const ulonglong2*>(&v[cur][1][k0]);
        const ulonglong2* vb2 = reinterpret_cast<const ulonglong2*>(&v[cur][2][k0]);
        const ulonglong2* vb3 = reinterpret_cast<const ulonglong2*>(&v[cur][3][k0]);

        #pragma unroll
        for (int i = 0; i < KQ / 4; i++) {   // 12 iters, 4 k's each
            ulonglong2 q0 = vb0[i];
            ulonglong2 q1 = vb1[i];
            ulonglong2 q2 = vb2[i];
            ulonglong2 q3 = vb3[i];
            acc[0][0] = ffma2(w2[2 * i],     q0.x, acc[0][0]);
            acc[0][1] = ffma2(w2[2 * i + 1], q0.y, acc[0][1]);
            acc[1][0] = ffma2(w2[2 * i],     q1.x, acc[1][0]);
            acc[1][1] = ffma2(w2[2 * i + 1], q1.y, acc[1][1]);
            acc[2][0] = ffma2(w2[2 * i],     q2.x, acc[2][0]);
            acc[2][1] = ffma2(w2[2 * i + 1], q2.y, acc[2][1]);
            acc[3][0] = ffma2(w2[2 * i],     q3.x, acc[3][0]);
            acc[3][1] = ffma2(w2[2 * i + 1], q3.y, acc[3][1]);
        }

        #pragma unroll
        for (int b = 0; b < BB; b++) {
            float2 p0 = unpack2(acc[b][0]);
            float2 p1 = unpack2(acc[b][1]);
            part[kh][b][j] = (p0.x + p0.y) + (p1.x + p1.y);
        }
        __syncthreads();

        // Combine quarters, activate, write h(t+1). All 512 threads busy:
        // thread (kh, j) handles batch kh (BB == NSPL == 4).
        {
            int b = kh;
            float z = part[0][b][j] + part[1][b][j] + part[2][b][j]
                    + part[3][b][j] + bias[j];
            v[nxt][b][INPT + j] = tanh_fast(z);
        }
        asm volatile("cp.async.wait_group 0;" ::);
        __syncthreads();
        cur = nxt;
    }

    // ---- output projection: out[b] = h_final[b] . W_out + b_out ----
    // cur == 0 after an even number of steps; final h lives in v[cur].
    if (tid < 4 * 32) {
        int b = tid >> 5;
        int l = tid & 31;
        float s = 0.0f;
        #pragma unroll
        for (int m = 0; m < 4; m++) {
            int jj = l + 32 * m;
            s += v[cur][b][INPT + jj] * W_out[jj];
        }
        #pragma unroll
        for (int off = 16; off; off >>= 1)
            s += __shfl_down_sync(0xffffffffu, s, off);
        if (l == 0) out[bbase + b] = s + b_out[0];
    }
}

extern "C" void kernel_launch(void* const* d_in, const int* in_sizes, int n_in,
                              void* d_out, int out_size) {
    const float* xs    = (const float*)d_in[0];
    const float* W_ih  = (const float*)d_in[1];
    const float* W_hh  = (const float*)d_in[2];
    const float* b_ih  = (const float*)d_in[3];
    const float* b_hh  = (const float*)d_in[4];
    const float* W_out = (const float*)d_in[5];
    const float* b_out = (const float*)d_in[6];
    rnn_kernel<<<NBLK, NTHR>>>(xs, W_ih, W_hh, b_ih, b_hh, W_out, b_out,
                               (float*)d_out);
}